// round 1
// baseline (speedup 1.0000x reference)
#include <cuda_runtime.h>
#include <math.h>

#define L_SEQ 4096
#define NHEAD 8
#define DIM   128
#define NQ    32      // 4096/128
#define NK    64      // 4096/64
#define TOPK  32

// ---------------- scratch (device globals; no allocation allowed) ----------
__device__ float fqg[L_SEQ * NHEAD * DIM];     // softmax feature of q
__device__ float fkg[L_SEQ * NHEAD * DIM];     // softmax feature of k
__device__ float kvg[NHEAD * DIM * DIM];       // fk^T v per head
__device__ float ksumg[NHEAD * DIM];           // sum fk over L
__device__ float Mg[NHEAD * DIM * DIM];        // kv @ W^T per head
__device__ float pqg[NHEAD * NQ * DIM];        // pooled q sums (x128)
__device__ float pkg[NHEAD * NK * DIM];        // pooled k sums (x64)
__device__ float mkg[NHEAD * DIM];             // mean_k over L
__device__ int   lutg[NHEAD * NQ * TOPK];      // selected K-block ids

// ---------------- zero accumulators ----------------------------------------
__global__ void zero_kernel() {
    int n = NHEAD * DIM * DIM + NHEAD * DIM;
    for (int i = blockIdx.x * blockDim.x + threadIdx.x; i < n;
         i += gridDim.x * blockDim.x) {
        if (i < NHEAD * DIM * DIM) kvg[i] = 0.f;
        else ksumg[i - NHEAD * DIM * DIM] = 0.f;
    }
}

// ---------------- row softmax over D for q and k ----------------------------
// grid (L, H), block 64: warp0 -> q row, warp1 -> k row
__global__ void row_softmax_kernel(const float* __restrict__ q,
                                   const float* __restrict__ k) {
    int l = blockIdx.x, h = blockIdx.y;
    int w = threadIdx.x >> 5, lane = threadIdx.x & 31;
    const float4* src = (const float4*)(w ? k : q);
    float4* dst = (float4*)(w ? fkg : fqg);
    int base = (l * NHEAD + h) * (DIM / 4) + lane;
    float4 v = src[base];
    float mx = fmaxf(fmaxf(v.x, v.y), fmaxf(v.z, v.w));
    #pragma unroll
    for (int o = 16; o; o >>= 1) mx = fmaxf(mx, __shfl_xor_sync(0xffffffffu, mx, o));
    float4 e;
    e.x = __expf(v.x - mx); e.y = __expf(v.y - mx);
    e.z = __expf(v.z - mx); e.w = __expf(v.w - mx);
    float s = e.x + e.y + e.z + e.w;
    #pragma unroll
    for (int o = 16; o; o >>= 1) s += __shfl_xor_sync(0xffffffffu, s, o);
    float inv = 1.f / s;
    e.x *= inv; e.y *= inv; e.z *= inv; e.w *= inv;
    dst[base] = e;
}

// ---------------- block pooling --------------------------------------------
// grid (NQ, H), block 128: pqg[h][qb][d] = sum over 128 rows of q
__global__ void pq_pool_kernel(const float* __restrict__ q) {
    int qb = blockIdx.x, h = blockIdx.y, d = threadIdx.x;
    float s = 0.f;
    int base = ((qb * 128) * NHEAD + h) * DIM + d;
    #pragma unroll 4
    for (int r = 0; r < 128; r++) s += q[base + r * NHEAD * DIM];
    pqg[(h * NQ + qb) * DIM + d] = s;
}

// grid (NK, H), block 128
__global__ void pk_pool_kernel(const float* __restrict__ k) {
    int kb = blockIdx.x, h = blockIdx.y, d = threadIdx.x;
    float s = 0.f;
    int base = ((kb * 64) * NHEAD + h) * DIM + d;
    #pragma unroll 4
    for (int r = 0; r < 64; r++) s += k[base + r * NHEAD * DIM];
    pkg[(h * NK + kb) * DIM + d] = s;
}

// grid H, block 128
__global__ void meank_kernel() {
    int h = blockIdx.x, d = threadIdx.x;
    float s = 0.f;
    #pragma unroll 4
    for (int kb = 0; kb < NK; kb++) s += pkg[(h * NK + kb) * DIM + d];
    mkg[h * DIM + d] = s * (1.f / (float)L_SEQ);
}

// ---------------- routing scores + top-32 selection -------------------------
// grid (NQ, H), block 128
__global__ void score_topk_kernel() {
    __shared__ float pqsh[DIM];
    __shared__ float mksh[DIM];
    __shared__ float pks[NK * 129];
    __shared__ float scores[NK];
    int qb = blockIdx.x, h = blockIdx.y, tid = threadIdx.x;
    pqsh[tid] = pqg[(h * NQ + qb) * DIM + tid];
    mksh[tid] = mkg[h * DIM + tid];
    for (int i = 0; i < 64; i++) {
        int idx = tid + i * 128;          // 0..8191
        int kb = idx >> 7, d = idx & 127;
        pks[kb * 129 + d] = pkg[(h * NK + kb) * DIM + d];
    }
    __syncthreads();
    if (tid < NK) {
        float sc = 0.f;
        #pragma unroll 4
        for (int d = 0; d < DIM; d++)
            sc += pqsh[d] * (pks[tid * 129 + d] * (1.f / 64.f) - mksh[d]);
        scores[tid] = sc;
    }
    __syncthreads();
    if (tid == 0) {
        unsigned long long used = 0ull;
        for (int i = 0; i < TOPK; i++) {
            float best = -INFINITY; int bidx = 0;
            for (int kb = 0; kb < NK; kb++) {
                if ((used >> kb) & 1ull) continue;
                if (scores[kb] > best) { best = scores[kb]; bidx = kb; }
            }
            used |= 1ull << bidx;
            lutg[(h * NQ + qb) * TOPK + i] = bidx;
        }
    }
}

// ---------------- kv = fk^T v per head (+ ksum) -----------------------------
// grid (64 chunks, H), block 256, dyn smem 64KB
__global__ void kv_kernel(const float* __restrict__ v) {
    extern __shared__ float sm[];
    float* fksh = sm;            // 64x128
    float* vsh  = sm + 8192;     // 64x128
    int tid = threadIdx.x, h = blockIdx.y;
    int l0 = blockIdx.x * 64;
    const float4* fk4 = (const float4*)fkg;
    const float4* v4  = (const float4*)v;
    #pragma unroll
    for (int i = 0; i < 8; i++) {
        int idx = tid + i * 256;
        int row = idx >> 5, d4 = idx & 31;
        int g = (l0 + row) * (NHEAD * DIM / 4) + h * 32 + d4;
        ((float4*)fksh)[row * 32 + d4] = fk4[g];
        ((float4*)vsh)[row * 32 + d4]  = v4[g];
    }
    __syncthreads();
    int d = tid >> 1, eh4 = (tid & 1) * 16;
    float4 acc[16];
    #pragma unroll
    for (int i = 0; i < 16; i++) acc[i] = make_float4(0.f, 0.f, 0.f, 0.f);
    float ks = 0.f;
    for (int r = 0; r < 64; r++) {
        float a = fksh[r * DIM + d];
        if ((tid & 1) == 0) ks += a;
        #pragma unroll
        for (int i = 0; i < 16; i++) {
            float4 vv = ((float4*)vsh)[r * 32 + eh4 + i];
            acc[i].x += a * vv.x; acc[i].y += a * vv.y;
            acc[i].z += a * vv.z; acc[i].w += a * vv.w;
        }
    }
    float* kvp = kvg + h * DIM * DIM + d * DIM + (tid & 1) * 64;
    #pragma unroll
    for (int i = 0; i < 16; i++) {
        atomicAdd(&kvp[i * 4 + 0], acc[i].x);
        atomicAdd(&kvp[i * 4 + 1], acc[i].y);
        atomicAdd(&kvp[i * 4 + 2], acc[i].z);
        atomicAdd(&kvp[i * 4 + 3], acc[i].w);
    }
    if ((tid & 1) == 0) atomicAdd(&ksumg[h * DIM + d], ks);
}

// ---------------- M = kv @ W^T per head ------------------------------------
// grid H, block 256, dyn smem 133632
__global__ void m_kernel(const float* __restrict__ w) {
    extern __shared__ float sm[];
    float* kvsh = sm;               // 128 x 129
    float* wts  = sm + 128 * 129;   // transposed W: [dp][e] stride 132
    int tid = threadIdx.x, h = blockIdx.x;
    for (int i = 0; i < 64; i++) {
        int idx = tid + i * 256;                // 0..16383
        int d = idx >> 7, dp = idx & 127;
        kvsh[d * 129 + dp] = kvg[h * DIM * DIM + idx];
        int e = idx >> 7, dpp = idx & 127;      // w[e][dpp]
        wts[dpp * 132 + e] = w[idx];
    }
    __syncthreads();
    int d = tid >> 1, eh4 = (tid & 1) * 16;
    float4 acc[16];
    #pragma unroll
    for (int i = 0; i < 16; i++) acc[i] = make_float4(0.f, 0.f, 0.f, 0.f);
    for (int dp = 0; dp < DIM; dp++) {
        float a = kvsh[d * 129 + dp];
        #pragma unroll
        for (int i = 0; i < 16; i++) {
            float4 wv = ((float4*)(wts + dp * 132))[eh4 + i];
            acc[i].x += a * wv.x; acc[i].y += a * wv.y;
            acc[i].z += a * wv.z; acc[i].w += a * wv.w;
        }
    }
    float4* mp = (float4*)(Mg + h * DIM * DIM + d * DIM + (tid & 1) * 64);
    #pragma unroll
    for (int i = 0; i < 16; i++) mp[i] = acc[i];
}

// ---------------- linear-attn output (writes d_out) -------------------------
// grid (L/16, H), block 128
__global__ void lin_out_kernel(const float* __restrict__ b,
                               float* __restrict__ out) {
    __shared__ float fqsh[16 * DIM];
    __shared__ float sden[16];
    int tid = threadIdx.x, h = blockIdx.y;
    int l0 = blockIdx.x * 16;
    float ks = ksumg[h * DIM + tid];
    if (tid < 16) sden[tid] = 0.f;
    #pragma unroll
    for (int r = 0; r < 16; r++)
        fqsh[r * DIM + tid] = fqg[((l0 + r) * NHEAD + h) * DIM + tid];
    __syncthreads();
    int lane = tid & 31;
    #pragma unroll
    for (int r = 0; r < 16; r++) {
        float val = fqsh[r * DIM + tid] * ks;
        #pragma unroll
        for (int o = 16; o; o >>= 1) val += __shfl_xor_sync(0xffffffffu, val, o);
        if (lane == 0) atomicAdd(&sden[r], val);
    }
    __syncthreads();
    float accs[16];
    #pragma unroll
    for (int r = 0; r < 16; r++) accs[r] = 0.f;
    const float* Mp = Mg + h * DIM * DIM + tid;
    #pragma unroll 4
    for (int d = 0; d < DIM; d++) {
        float m = Mp[d * DIM];
        #pragma unroll
        for (int r = 0; r < 16; r++) accs[r] += fqsh[r * DIM + d] * m;
    }
    float be = b[tid];
    #pragma unroll
    for (int r = 0; r < 16; r++) {
        float inv = 1.f / (1e-5f + sden[r]);
        out[((l0 + r) * NHEAD + h) * DIM + tid] = accs[r] * inv + be;
    }
}

// ---------------- block-sparse attention (adds into d_out) ------------------
// grid (2, NQ, H), block 256, dyn smem 114944
__global__ void sparse_attn_kernel(const float* __restrict__ q,
                                   const float* __restrict__ k,
                                   const float* __restrict__ v,
                                   float* __restrict__ out) {
    extern __shared__ float sm[];
    float* Qs = sm;            // 64x128 f4-swizzled
    float* Ks = sm + 8192;
    float* Vs = sm + 16384;
    float* Ss = sm + 24576;    // 64x65 scores/probs
    const int tid = threadIdx.x;
    const int half = blockIdx.x, qb = blockIdx.y, h = blockIdx.z;
    const int l0 = qb * 128 + half * 64;
    const float scale = 0.08838834764831845f;  // 1/sqrt(128)
    const float4* q4 = (const float4*)q;
    const float4* k4 = (const float4*)k;
    const float4* v4 = (const float4*)v;
    float4* Qs4 = (float4*)Qs;
    float4* Ks4 = (float4*)Ks;
    float4* Vs4 = (float4*)Vs;

    #pragma unroll
    for (int i = 0; i < 8; i++) {
        int idx = tid + i * 256;
        int row = idx >> 5, d4 = idx & 31;
        float4 val = q4[(l0 + row) * 256 + h * 32 + d4];
        val.x *= scale; val.y *= scale; val.z *= scale; val.w *= scale;
        Qs4[row * 32 + (d4 ^ (row & 31))] = val;
    }

    const int jgrp = tid & 7, qp = tid >> 3;   // score mapping (2 q x 8 k)
    const int qy = tid >> 2, dp = tid & 3;     // pv mapping (1 q x 32 dims)
    float m = -INFINITY, lsum = 0.f;
    float4 acc[8];
    #pragma unroll
    for (int i = 0; i < 8; i++) acc[i] = make_float4(0.f, 0.f, 0.f, 0.f);
    const int* lrow = lutg + (h * NQ + qb) * TOPK;

    for (int t = 0; t < TOPK; t++) {
        int kb = lrow[t];
        int kl0 = kb * 64;
        __syncthreads();
        #pragma unroll
        for (int i = 0; i < 8; i++) {
            int idx = tid + i * 256;
            int row = idx >> 5, d4 = idx & 31;
            int sw = row * 32 + (d4 ^ (row & 31));
            int g = (kl0 + row) * 256 + h * 32 + d4;
            Ks4[sw] = k4[g];
            Vs4[sw] = v4[g];
        }
        __syncthreads();
        // ---- scores: each thread 2 queries x 8 keys ----
        float s0[8], s1[8];
        #pragma unroll
        for (int jj = 0; jj < 8; jj++) { s0[jj] = 0.f; s1[jj] = 0.f; }
        const int qy0 = qp, qy1 = qp + 32;
        #pragma unroll 4
        for (int d4 = 0; d4 < 32; d4++) {
            float4 qv0 = Qs4[qy0 * 32 + (d4 ^ (qy0 & 31))];
            float4 qv1 = Qs4[qy1 * 32 + (d4 ^ (qy1 & 31))];
            #pragma unroll
            for (int jj = 0; jj < 8; jj++) {
                int j = jgrp * 8 + jj;
                float4 kv = Ks4[j * 32 + (d4 ^ (j & 31))];
                s0[jj] += qv0.x * kv.x + qv0.y * kv.y + qv0.z * kv.z + qv0.w * kv.w;
                s1[jj] += qv1.x * kv.x + qv1.y * kv.y + qv1.z * kv.z + qv1.w * kv.w;
            }
        }
        #pragma unroll
        for (int jj = 0; jj < 8; jj++) {
            Ss[qy0 * 65 + jgrp * 8 + jj] = s0[jj];
            Ss[qy1 * 65 + jgrp * 8 + jj] = s1[jj];
        }
        __syncthreads();
        // ---- online softmax (pv mapping, 4 lanes per query) ----
        float mx = -INFINITY;
        #pragma unroll
        for (int i = 0; i < 16; i++)
            mx = fmaxf(mx, Ss[qy * 65 + dp * 16 + i]);
        mx = fmaxf(mx, __shfl_xor_sync(0xffffffffu, mx, 1));
        mx = fmaxf(mx, __shfl_xor_sync(0xffffffffu, mx, 2));
        float mnew = fmaxf(m, mx);
        float corr = __expf(m - mnew);
        float ps = 0.f;
        #pragma unroll
        for (int i = 0; i < 16; i++) {
            float p = __expf(Ss[qy * 65 + dp * 16 + i] - mnew);
            Ss[qy * 65 + dp * 16 + i] = p;
            ps += p;
        }
        ps += __shfl_xor_sync(0xffffffffu, ps, 1);
        ps += __shfl_xor_sync(0xffffffffu, ps, 2);
        lsum = lsum * corr + ps;
        m = mnew;
        #pragma unroll
        for (int i = 0; i < 8; i++) {
            acc[i].x *= corr; acc[i].y *= corr;
            acc[i].z *= corr; acc[i].w *= corr;
        }
        __syncwarp();
        // ---- PV ----
        #pragma unroll 4
        for (int j = 0; j < 64; j++) {
            float p = Ss[qy * 65 + j];
            #pragma unroll
            for (int i = 0; i < 8; i++) {
                int d4 = dp * 8 + i;
                float4 vv = Vs4[j * 32 + (d4 ^ (j & 31))];
                acc[i].x += p * vv.x; acc[i].y += p * vv.y;
                acc[i].z += p * vv.z; acc[i].w += p * vv.w;
            }
        }
    }
    float inv = 1.f / lsum;
    float4* out4 = (float4*)out;
    #pragma unroll
    for (int i = 0; i < 8; i++) {
        int d4 = dp * 8 + i;
        long o = (long)(l0 + qy) * 256 + h * 32 + d4;
        float4 cur = out4[o];
        cur.x += acc[i].x * inv; cur.y += acc[i].y * inv;
        cur.z += acc[i].z * inv; cur.w += acc[i].w * inv;
        out4[o] = cur;
    }
}

// ---------------- launch -----------------------------------------------------
extern "C" void kernel_launch(void* const* d_in, const int* in_sizes, int n_in,
                              void* d_out, int out_size) {
    const float* q = (const float*)d_in[0];
    const float* k = (const float*)d_in[1];
    const float* v = (const float*)d_in[2];
    const float* w = (const float*)d_in[3];
    const float* b = (const float*)d_in[4];
    float* out = (float*)d_out;

    cudaFuncSetAttribute(kv_kernel, cudaFuncAttributeMaxDynamicSharedMemorySize, 65536);
    cudaFuncSetAttribute(m_kernel, cudaFuncAttributeMaxDynamicSharedMemorySize, 133632);
    cudaFuncSetAttribute(sparse_attn_kernel, cudaFuncAttributeMaxDynamicSharedMemorySize, 114944);

    zero_kernel<<<64, 256>>>();
    row_softmax_kernel<<<dim3(L_SEQ, NHEAD), 64>>>(q, k);
    pq_pool_kernel<<<dim3(NQ, NHEAD), 128>>>(q);
    pk_pool_kernel<<<dim3(NK, NHEAD), 128>>>(k);
    meank_kernel<<<NHEAD, 128>>>();
    score_topk_kernel<<<dim3(NQ, NHEAD), 128>>>();
    kv_kernel<<<dim3(64, NHEAD), 256, 65536>>>(v);
    m_kernel<<<NHEAD, 256, 133632>>>(w);
    lin_out_kernel<<<dim3(L_SEQ / 16, NHEAD), 128>>>(b, out);
    sparse_attn_kernel<<<dim3(2, NQ, NHEAD), 256, 114944>>>(q, k, v, out);
}

// round 2
// speedup vs baseline: 1.6012x; 1.6012x over previous
#include <cuda_runtime.h>
#include <math.h>

#define L_SEQ 4096
#define NHEAD 8
#define DIM   128
#define NQ    32      // 4096/128
#define NK    64      // 4096/64
#define TOPK  32

// ---------------- scratch (device globals; no allocation allowed) ----------
__device__ float fqg[L_SEQ * NHEAD * DIM];     // softmax feature of q
__device__ float fkg[L_SEQ * NHEAD * DIM];     // softmax feature of k
__device__ float kvg[NHEAD * DIM * DIM];       // fk^T v per head
__device__ float ksumg[NHEAD * DIM];           // sum fk over L
__device__ float Mg[NHEAD * DIM * DIM];        // kv @ W^T per head
__device__ float pqg[NHEAD * NQ * DIM];        // pooled q sums (x128)
__device__ float pkg[NHEAD * NK * DIM];        // pooled k sums (x64)
__device__ float mkg[NHEAD * DIM];             // mean_k over L
__device__ int   lutg[NHEAD * NQ * TOPK];      // selected K-block ids

// ---------------- f32x2 packed-math helpers (Blackwell) ---------------------
typedef unsigned long long u64;

__device__ __forceinline__ u64 ffma2(u64 a, u64 b, u64 c) {
    u64 d;
    asm("fma.rn.f32x2 %0, %1, %2, %3;" : "=l"(d) : "l"(a), "l"(b), "l"(c));
    return d;
}
__device__ __forceinline__ u64 fmul2(u64 a, u64 b) {
    u64 d;
    asm("mul.rn.f32x2 %0, %1, %2;" : "=l"(d) : "l"(a), "l"(b));
    return d;
}
__device__ __forceinline__ u64 pkdup(float x) {
    u64 r;
    asm("mov.b64 %0, {%1, %1};" : "=l"(r) : "f"(x));
    return r;
}
__device__ __forceinline__ float2 unpk(u64 a) {
    float2 f;
    asm("mov.b64 {%0, %1}, %2;" : "=f"(f.x), "=f"(f.y) : "l"(a));
    return f;
}

#define CP_ASYNC16(dst, src) \
    asm volatile("cp.async.cg.shared.global [%0], [%1], 16;" :: "r"(dst), "l"(src))
#define CP_COMMIT() asm volatile("cp.async.commit_group;")

// ---------------- zero accumulators ----------------------------------------
__global__ void zero_kernel() {
    int n = NHEAD * DIM * DIM + NHEAD * DIM;
    for (int i = blockIdx.x * blockDim.x + threadIdx.x; i < n;
         i += gridDim.x * blockDim.x) {
        if (i < NHEAD * DIM * DIM) kvg[i] = 0.f;
        else ksumg[i - NHEAD * DIM * DIM] = 0.f;
    }
}

// ---------------- row softmax over D for q and k ----------------------------
__global__ void row_softmax_kernel(const float* __restrict__ q,
                                   const float* __restrict__ k) {
    int l = blockIdx.x, h = blockIdx.y;
    int w = threadIdx.x >> 5, lane = threadIdx.x & 31;
    const float4* src = (const float4*)(w ? k : q);
    float4* dst = (float4*)(w ? fkg : fqg);
    int base = (l * NHEAD + h) * (DIM / 4) + lane;
    float4 v = src[base];
    float mx = fmaxf(fmaxf(v.x, v.y), fmaxf(v.z, v.w));
    #pragma unroll
    for (int o = 16; o; o >>= 1) mx = fmaxf(mx, __shfl_xor_sync(0xffffffffu, mx, o));
    float4 e;
    e.x = __expf(v.x - mx); e.y = __expf(v.y - mx);
    e.z = __expf(v.z - mx); e.w = __expf(v.w - mx);
    float s = e.x + e.y + e.z + e.w;
    #pragma unroll
    for (int o = 16; o; o >>= 1) s += __shfl_xor_sync(0xffffffffu, s, o);
    float inv = 1.f / s;
    e.x *= inv; e.y *= inv; e.z *= inv; e.w *= inv;
    dst[base] = e;
}

// ---------------- block pooling --------------------------------------------
__global__ void pq_pool_kernel(const float* __restrict__ q) {
    int qb = blockIdx.x, h = blockIdx.y, d = threadIdx.x;
    float s = 0.f;
    int base = ((qb * 128) * NHEAD + h) * DIM + d;
    #pragma unroll 4
    for (int r = 0; r < 128; r++) s += q[base + r * NHEAD * DIM];
    pqg[(h * NQ + qb) * DIM + d] = s;
}

__global__ void pk_pool_kernel(const float* __restrict__ k) {
    int kb = blockIdx.x, h = blockIdx.y, d = threadIdx.x;
    float s = 0.f;
    int base = ((kb * 64) * NHEAD + h) * DIM + d;
    #pragma unroll 4
    for (int r = 0; r < 64; r++) s += k[base + r * NHEAD * DIM];
    pkg[(h * NK + kb) * DIM + d] = s;
}

__global__ void meank_kernel() {
    int h = blockIdx.x, d = threadIdx.x;
    float s = 0.f;
    #pragma unroll 4
    for (int kb = 0; kb < NK; kb++) s += pkg[(h * NK + kb) * DIM + d];
    mkg[h * DIM + d] = s * (1.f / (float)L_SEQ);
}

// ---------------- routing scores + top-32 selection -------------------------
__global__ void score_topk_kernel() {
    __shared__ float pqsh[DIM];
    __shared__ float mksh[DIM];
    __shared__ float pks[NK * 129];
    __shared__ float scores[NK];
    int qb = blockIdx.x, h = blockIdx.y, tid = threadIdx.x;
    pqsh[tid] = pqg[(h * NQ + qb) * DIM + tid];
    mksh[tid] = mkg[h * DIM + tid];
    for (int i = 0; i < 64; i++) {
        int idx = tid + i * 128;
        int kb = idx >> 7, d = idx & 127;
        pks[kb * 129 + d] = pkg[(h * NK + kb) * DIM + d];
    }
    __syncthreads();
    if (tid < NK) {
        float sc = 0.f;
        #pragma unroll 4
        for (int d = 0; d < DIM; d++)
            sc += pqsh[d] * (pks[tid * 129 + d] * (1.f / 64.f) - mksh[d]);
        scores[tid] = sc;
    }
    __syncthreads();
    if (tid == 0) {
        unsigned long long used = 0ull;
        for (int i = 0; i < TOPK; i++) {
            float best = -INFINITY; int bidx = 0;
            for (int kb = 0; kb < NK; kb++) {
                if ((used >> kb) & 1ull) continue;
                if (scores[kb] > best) { best = scores[kb]; bidx = kb; }
            }
            used |= 1ull << bidx;
            lutg[(h * NQ + qb) * TOPK + i] = bidx;
        }
    }
}

// ---------------- kv = fk^T v per head (+ ksum) -----------------------------
__global__ void kv_kernel(const float* __restrict__ v) {
    extern __shared__ float sm[];
    float* fksh = sm;            // 64x128
    float* vsh  = sm + 8192;     // 64x128
    int tid = threadIdx.x, h = blockIdx.y;
    int l0 = blockIdx.x * 64;
    const float4* fk4 = (const float4*)fkg;
    const float4* v4  = (const float4*)v;
    #pragma unroll
    for (int i = 0; i < 8; i++) {
        int idx = tid + i * 256;
        int row = idx >> 5, d4 = idx & 31;
        int g = (l0 + row) * (NHEAD * DIM / 4) + h * 32 + d4;
        ((float4*)fksh)[row * 32 + d4] = fk4[g];
        ((float4*)vsh)[row * 32 + d4]  = v4[g];
    }
    __syncthreads();
    int d = tid >> 1, eh4 = (tid & 1) * 16;
    float4 acc[16];
    #pragma unroll
    for (int i = 0; i < 16; i++) acc[i] = make_float4(0.f, 0.f, 0.f, 0.f);
    float ks = 0.f;
    for (int r = 0; r < 64; r++) {
        float a = fksh[r * DIM + d];
        if ((tid & 1) == 0) ks += a;
        #pragma unroll
        for (int i = 0; i < 16; i++) {
            float4 vv = ((float4*)vsh)[r * 32 + eh4 + i];
            acc[i].x += a * vv.x; acc[i].y += a * vv.y;
            acc[i].z += a * vv.z; acc[i].w += a * vv.w;
        }
    }
    float* kvp = kvg + h * DIM * DIM + d * DIM + (tid & 1) * 64;
    #pragma unroll
    for (int i = 0; i < 16; i++) {
        atomicAdd(&kvp[i * 4 + 0], acc[i].x);
        atomicAdd(&kvp[i * 4 + 1], acc[i].y);
        atomicAdd(&kvp[i * 4 + 2], acc[i].z);
        atomicAdd(&kvp[i * 4 + 3], acc[i].w);
    }
    if ((tid & 1) == 0) atomicAdd(&ksumg[h * DIM + d], ks);
}

// ---------------- M = kv @ W^T per head ------------------------------------
__global__ void m_kernel(const float* __restrict__ w) {
    extern __shared__ float sm[];
    float* kvsh = sm;               // 128 x 129
    float* wts  = sm + 128 * 129;   // transposed W
    int tid = threadIdx.x, h = blockIdx.x;
    for (int i = 0; i < 64; i++) {
        int idx = tid + i * 256;
        int d = idx >> 7, dp = idx & 127;
        kvsh[d * 129 + dp] = kvg[h * DIM * DIM + idx];
        int dpp = idx & 127;
        wts[dpp * 132 + (idx >> 7)] = w[idx];
    }
    __syncthreads();
    int d = tid >> 1, eh4 = (tid & 1) * 16;
    float4 acc[16];
    #pragma unroll
    for (int i = 0; i < 16; i++) acc[i] = make_float4(0.f, 0.f, 0.f, 0.f);
    for (int dp = 0; dp < DIM; dp++) {
        float a = kvsh[d * 129 + dp];
        #pragma unroll
        for (int i = 0; i < 16; i++) {
            float4 wv = ((float4*)(wts + dp * 132))[eh4 + i];
            acc[i].x += a * wv.x; acc[i].y += a * wv.y;
            acc[i].z += a * wv.z; acc[i].w += a * wv.w;
        }
    }
    float4* mp = (float4*)(Mg + h * DIM * DIM + d * DIM + (tid & 1) * 64);
    #pragma unroll
    for (int i = 0; i < 16; i++) mp[i] = acc[i];
}

// ---------------- linear-attn output (writes d_out) -------------------------
__global__ void lin_out_kernel(const float* __restrict__ b,
                               float* __restrict__ out) {
    __shared__ float fqsh[16 * DIM];
    __shared__ float sden[16];
    int tid = threadIdx.x, h = blockIdx.y;
    int l0 = blockIdx.x * 16;
    float ks = ksumg[h * DIM + tid];
    if (tid < 16) sden[tid] = 0.f;
    #pragma unroll
    for (int r = 0; r < 16; r++)
        fqsh[r * DIM + tid] = fqg[((l0 + r) * NHEAD + h) * DIM + tid];
    __syncthreads();
    int lane = tid & 31;
    #pragma unroll
    for (int r = 0; r < 16; r++) {
        float val = fqsh[r * DIM + tid] * ks;
        #pragma unroll
        for (int o = 16; o; o >>= 1) val += __shfl_xor_sync(0xffffffffu, val, o);
        if (lane == 0) atomicAdd(&sden[r], val);
    }
    __syncthreads();
    float accs[16];
    #pragma unroll
    for (int r = 0; r < 16; r++) accs[r] = 0.f;
    const float* Mp = Mg + h * DIM * DIM + tid;
    #pragma unroll 4
    for (int d = 0; d < DIM; d++) {
        float m = Mp[d * DIM];
        #pragma unroll
        for (int r = 0; r < 16; r++) accs[r] += fqsh[r * DIM + d] * m;
    }
    float be = b[tid];
    #pragma unroll
    for (int r = 0; r < 16; r++) {
        float inv = 1.f / (1e-5f + sden[r]);
        out[((l0 + r) * NHEAD + h) * DIM + tid] = accs[r] * inv + be;
    }
}

// ---------------- block-sparse attention v2 (adds into d_out) ---------------
// grid (NQ, NHEAD), block 512, smem 229888
// 128 queries/CTA; 32 tiles of 64 keys; cp.async double-buffered K/V;
// conflict-free LDS; f32x2 packed FMA.
__global__ void __launch_bounds__(512, 1)
sparse_attn_kernel(const float* __restrict__ q,
                   const float* __restrict__ k,
                   const float* __restrict__ v,
                   float* __restrict__ out) {
    extern __shared__ float sm[];
    float4* Qs4 = (float4*)sm;                    // [0, 4096) f4
    float4* Kb4 = (float4*)sm + 4096;             // 2 x 2048 f4
    float4* Vb4 = (float4*)sm + 8192;             // 2 x 2048 f4
    float*  Ss  = sm + 49152;                     // 128 x 65 floats

    const int tid = threadIdx.x;
    const int qb = blockIdx.x, h = blockIdx.y;
    const int l0 = qb * 128;
    const float scale = 0.08838834764831845f;     // 1/sqrt(128)
    const float4* q4 = (const float4*)q;
    const float4* k4 = (const float4*)k;
    const float4* v4 = (const float4*)v;
    const int* lrow = lutg + (h * NQ + qb) * TOPK;

    unsigned smem_u32 = (unsigned)__cvta_generic_to_shared(sm);

    // ---- issue tile 0 K/V loads ----
    {
        int kb = lrow[0];
        int gbase = kb * 64 * 256 + h * 32;
        #pragma unroll
        for (int i = 0; i < 4; i++) {
            int idx = tid + i * 512;              // 0..2047
            int row = idx >> 5, d4 = idx & 31;
            int sw = row * 32 + (d4 ^ (row & 31));
            CP_ASYNC16(smem_u32 + (4096 + sw) * 16, (const void*)(k4 + gbase + row * 256 + d4));
            CP_ASYNC16(smem_u32 + (8192 + sw) * 16, (const void*)(v4 + gbase + row * 256 + d4));
        }
        CP_COMMIT();
    }

    // ---- load Q (scaled, swizzled) ----
    #pragma unroll
    for (int i = 0; i < 8; i++) {
        int idx = tid + i * 512;                  // 0..4095
        int row = idx >> 5, d4 = idx & 31;
        float4 val = q4[(l0 + row) * 256 + h * 32 + d4];
        val.x *= scale; val.y *= scale; val.z *= scale; val.w *= scale;
        Qs4[row * 32 + (d4 ^ (row & 31))] = val;
    }

    // score mapping: 2 queries x 8 keys per thread (keys stride 8)
    const int jgrp = tid & 7, qp = tid >> 3;      // qp 0..63 -> rows qp, qp+64
    // softmax/pv mapping: 1 query x 32 dims per thread
    const int qy = tid >> 2, dp = tid & 3;

    float m = -INFINITY, lsum = 0.f;
    ulonglong2 acc2[8];
    #pragma unroll
    for (int i = 0; i < 8; i++) { acc2[i].x = 0ull; acc2[i].y = 0ull; }

    for (int t = 0; t < TOPK; t++) {
        const float4* Kc = Kb4 + (t & 1) * 2048;
        const float4* Vc = Vb4 + (t & 1) * 2048;

        __syncthreads();   // prev compute done: buffers + Ss reusable
        if (t + 1 < TOPK) {
            int kb = lrow[t + 1];
            int gbase = kb * 64 * 256 + h * 32;
            int boff = ((t + 1) & 1) * 2048;
            #pragma unroll
            for (int i = 0; i < 4; i++) {
                int idx = tid + i * 512;
                int row = idx >> 5, d4 = idx & 31;
                int sw = boff + row * 32 + (d4 ^ (row & 31));
                CP_ASYNC16(smem_u32 + (4096 + sw) * 16, (const void*)(k4 + gbase + row * 256 + d4));
                CP_ASYNC16(smem_u32 + (8192 + sw) * 16, (const void*)(v4 + gbase + row * 256 + d4));
            }
            CP_COMMIT();
            asm volatile("cp.async.wait_group 1;");
        } else {
            asm volatile("cp.async.wait_group 0;");
        }
        __syncthreads();   // tile t visible

        // ---- scores: 2q x 8k, f32x2 ----
        {
            u64 sA[8], sB[8];
            #pragma unroll
            for (int jj = 0; jj < 8; jj++) { sA[jj] = 0ull; sB[jj] = 0ull; }
            const int qy0 = qp, qy1 = qp + 64;
            const int xm0 = qy0 & 31;             // note (qy1 & 31) == xm0
            #pragma unroll 4
            for (int d4 = 0; d4 < 32; d4++) {
                ulonglong2 q0 = *(const ulonglong2*)&Qs4[qy0 * 32 + (d4 ^ xm0)];
                ulonglong2 q1 = *(const ulonglong2*)&Qs4[qy1 * 32 + (d4 ^ xm0)];
                #pragma unroll
                for (int jj = 0; jj < 8; jj++) {
                    int j = jgrp + jj * 8;
                    ulonglong2 kv = *(const ulonglong2*)&Kc[j * 32 + (d4 ^ (j & 31))];
                    sA[jj] = ffma2(q0.x, kv.x, sA[jj]);
                    sA[jj] = ffma2(q0.y, kv.y, sA[jj]);
                    sB[jj] = ffma2(q1.x, kv.x, sB[jj]);
                    sB[jj] = ffma2(q1.y, kv.y, sB[jj]);
                }
            }
            #pragma unroll
            for (int jj = 0; jj < 8; jj++) {
                float2 a = unpk(sA[jj]);
                float2 b2 = unpk(sB[jj]);
                Ss[qy0 * 65 + jgrp + jj * 8] = a.x + a.y;
                Ss[qy1 * 65 + jgrp + jj * 8] = b2.x + b2.y;
            }
        }
        __syncthreads();

        // ---- online softmax (4 lanes per query) ----
        float mx = -INFINITY;
        #pragma unroll
        for (int i = 0; i < 16; i++)
            mx = fmaxf(mx, Ss[qy * 65 + dp * 16 + i]);
        mx = fmaxf(mx, __shfl_xor_sync(0xffffffffu, mx, 1));
        mx = fmaxf(mx, __shfl_xor_sync(0xffffffffu, mx, 2));
        float mnew = fmaxf(m, mx);
        float corr = __expf(m - mnew);
        float ps = 0.f;
        #pragma unroll
        for (int i = 0; i < 16; i++) {
            float p = __expf(Ss[qy * 65 + dp * 16 + i] - mnew);
            Ss[qy * 65 + dp * 16 + i] = p;
            ps += p;
        }
        ps += __shfl_xor_sync(0xffffffffu, ps, 1);
        ps += __shfl_xor_sync(0xffffffffu, ps, 2);
        lsum = lsum * corr + ps;
        m = mnew;
        u64 corr2 = pkdup(corr);
        #pragma unroll
        for (int i = 0; i < 8; i++) {
            acc2[i].x = fmul2(acc2[i].x, corr2);
            acc2[i].y = fmul2(acc2[i].y, corr2);
        }
        __syncwarp();

        // ---- PV: 1q x 32 dims, f32x2 ----
        #pragma unroll 4
        for (int j = 0; j < 64; j++) {
            u64 pp = pkdup(Ss[qy * 65 + j]);
            #pragma unroll
            for (int i = 0; i < 8; i++) {
                int d4 = dp * 8 + i;
                ulonglong2 vv = *(const ulonglong2*)&Vc[j * 32 + (d4 ^ (j & 31))];
                acc2[i].x = ffma2(pp, vv.x, acc2[i].x);
                acc2[i].y = ffma2(pp, vv.y, acc2[i].y);
            }
        }
    }

    float inv = 1.f / lsum;
    float4* out4 = (float4*)out;
    #pragma unroll
    for (int i = 0; i < 8; i++) {
        int d4 = dp * 8 + i;
        long o = (long)(l0 + qy) * 256 + h * 32 + d4;
        float4 cur = out4[o];
        float2 a = unpk(acc2[i].x);
        float2 b2 = unpk(acc2[i].y);
        cur.x += a.x * inv; cur.y += a.y * inv;
        cur.z += b2.x * inv; cur.w += b2.y * inv;
        out4[o] = cur;
    }
}

// ---------------- launch -----------------------------------------------------
extern "C" void kernel_launch(void* const* d_in, const int* in_sizes, int n_in,
                              void* d_out, int out_size) {
    const float* q = (const float*)d_in[0];
    const float* k = (const float*)d_in[1];
    const float* v = (const float*)d_in[2];
    const float* w = (const float*)d_in[3];
    const float* b = (const float*)d_in[4];
    float* out = (float*)d_out;

    cudaFuncSetAttribute(kv_kernel, cudaFuncAttributeMaxDynamicSharedMemorySize, 65536);
    cudaFuncSetAttribute(m_kernel, cudaFuncAttributeMaxDynamicSharedMemorySize, 133632);
    cudaFuncSetAttribute(sparse_attn_kernel, cudaFuncAttributeMaxDynamicSharedMemorySize, 229888);

    zero_kernel<<<64, 256>>>();
    row_softmax_kernel<<<dim3(L_SEQ, NHEAD), 64>>>(q, k);
    pq_pool_kernel<<<dim3(NQ, NHEAD), 128>>>(q);
    pk_pool_kernel<<<dim3(NK, NHEAD), 128>>>(k);
    meank_kernel<<<NHEAD, 128>>>();
    score_topk_kernel<<<dim3(NQ, NHEAD), 128>>>();
    kv_kernel<<<dim3(64, NHEAD), 256, 65536>>>(v);
    m_kernel<<<NHEAD, 256, 133632>>>(w);
    lin_out_kernel<<<dim3(L_SEQ / 16, NHEAD), 128>>>(b, out);
    sparse_attn_kernel<<<dim3(NQ, NHEAD), 512, 229888>>>(q, k, v, out);
}

// round 7
// speedup vs baseline: 16.5299x; 10.3236x over previous
#include <cuda_runtime.h>
#include <cuda_fp16.h>
#include <math.h>

#define L_SEQ 4096
#define NHEAD 8
#define DIM   128
#define NQ    32      // 4096/128
#define NK    64      // 4096/64
#define TOPK  32

typedef unsigned int u32;
typedef unsigned long long u64;

// ---------------- scratch (device globals; no allocation allowed) ----------
__device__ float fqg[L_SEQ * NHEAD * DIM];     // softmax feature of q
__device__ float fkg[L_SEQ * NHEAD * DIM];     // softmax feature of k
__device__ float kvg[NHEAD * DIM * DIM];       // fk^T v per head
__device__ float ksumg[NHEAD * DIM];           // sum fk over L
__device__ float Mg[NHEAD * DIM * DIM];        // kv @ W^T per head
__device__ float pqg[NHEAD * NQ * DIM];        // pooled q sums (x128)
__device__ float pkg[NHEAD * NK * DIM];        // pooled k sums (x64)
__device__ float mkg[NHEAD * DIM];             // mean_k over L
__device__ int   lutg[NHEAD * NQ * TOPK];      // selected K-block ids
__device__ u32   ktg[NHEAD * NK * 64 * DIM];   // K as tf32, tile-major [h][kb][key][d]
__device__ u32   vtg[NHEAD * NK * DIM * 32];   // V as half2 pairs [h][kb][d][keypair]

// ---------------- helpers ---------------------------------------------------
__device__ __forceinline__ u32 f2tf32(float f) {
    u32 r; asm("cvt.rna.tf32.f32 %0, %1;" : "=r"(r) : "f"(f)); return r;
}
__device__ __forceinline__ u32 pack_half2(float lo, float hi) {
    __half2 h = __floats2half2_rn(lo, hi);
    return *(u32*)&h;
}
__device__ __forceinline__ void mma_tf32(float* c, const u32* a, u32 b0, u32 b1) {
    asm volatile("mma.sync.aligned.m16n8k8.row.col.f32.tf32.tf32.f32 "
        "{%0,%1,%2,%3}, {%4,%5,%6,%7}, {%8,%9}, {%0,%1,%2,%3};"
        : "+f"(c[0]), "+f"(c[1]), "+f"(c[2]), "+f"(c[3])
        : "r"(a[0]), "r"(a[1]), "r"(a[2]), "r"(a[3]), "r"(b0), "r"(b1));
}
__device__ __forceinline__ void mma_f16(float* c, const u32* a, u32 b0, u32 b1) {
    asm volatile("mma.sync.aligned.m16n8k16.row.col.f32.f16.f16.f32 "
        "{%0,%1,%2,%3}, {%4,%5,%6,%7}, {%8,%9}, {%0,%1,%2,%3};"
        : "+f"(c[0]), "+f"(c[1]), "+f"(c[2]), "+f"(c[3])
        : "r"(a[0]), "r"(a[1]), "r"(a[2]), "r"(a[3]), "r"(b0), "r"(b1));
}
#define CP_ASYNC16(dst, src) \
    asm volatile("cp.async.cg.shared.global [%0], [%1], 16;" :: "r"(dst), "l"(src))
#define CP_COMMIT() asm volatile("cp.async.commit_group;")

// ---------------- zero accumulators ----------------------------------------
__global__ void zero_kernel() {
    int n = NHEAD * DIM * DIM + NHEAD * DIM;
    for (int i = blockIdx.x * blockDim.x + threadIdx.x; i < n;
         i += gridDim.x * blockDim.x) {
        if (i < NHEAD * DIM * DIM) kvg[i] = 0.f;
        else ksumg[i - NHEAD * DIM * DIM] = 0.f;
    }
}

// ---------------- K/V tile pre-conversion -----------------------------------
// grid (NK, NHEAD), block 256. K -> tf32 tile-major; V -> fp16 transposed.
__global__ void prep_kv_kernel(const float* __restrict__ k,
                               const float* __restrict__ v) {
    __shared__ float vsm[64 * 129];
    int kb = blockIdx.x, h = blockIdx.y, tid = threadIdx.x;
    #pragma unroll 4
    for (int j = 0; j < 32; j++) {
        int idx = tid + j * 256;           // 0..8191
        int r = idx >> 7, d = idx & 127;
        float kvv;
        int g = ((kb * 64 + r) * NHEAD + h) * DIM + d;
        kvv = k[g];
        ktg[((h * NK + kb) * 64 + r) * DIM + d] = f2tf32(kvv);
        vsm[r * 129 + d] = v[g];
    }
    __syncthreads();
    #pragma unroll 4
    for (int j = 0; j < 16; j++) {
        int idx = tid + j * 256;           // 0..4095
        int d = idx >> 5, rp = idx & 31;
        vtg[((h * NK + kb) * DIM + d) * 32 + rp] =
            pack_half2(vsm[(2 * rp) * 129 + d], vsm[(2 * rp + 1) * 129 + d]);
    }
}

// ---------------- row softmax over D for q and k ----------------------------
__global__ void row_softmax_kernel(const float* __restrict__ q,
                                   const float* __restrict__ k) {
    int l = blockIdx.x, h = blockIdx.y;
    int w = threadIdx.x >> 5, lane = threadIdx.x & 31;
    const float4* src = (const float4*)(w ? k : q);
    float4* dst = (float4*)(w ? fkg : fqg);
    int base = (l * NHEAD + h) * (DIM / 4) + lane;
    float4 v = src[base];
    float mx = fmaxf(fmaxf(v.x, v.y), fmaxf(v.z, v.w));
    #pragma unroll
    for (int o = 16; o; o >>= 1) mx = fmaxf(mx, __shfl_xor_sync(0xffffffffu, mx, o));
    float4 e;
    e.x = __expf(v.x - mx); e.y = __expf(v.y - mx);
    e.z = __expf(v.z - mx); e.w = __expf(v.w - mx);
    float s = e.x + e.y + e.z + e.w;
    #pragma unroll
    for (int o = 16; o; o >>= 1) s += __shfl_xor_sync(0xffffffffu, s, o);
    float inv = 1.f / s;
    e.x *= inv; e.y *= inv; e.z *= inv; e.w *= inv;
    dst[base] = e;
}

// ---------------- block pooling --------------------------------------------
__global__ void pq_pool_kernel(const float* __restrict__ q) {
    int qb = blockIdx.x, h = blockIdx.y, d = threadIdx.x;
    float s = 0.f;
    int base = ((qb * 128) * NHEAD + h) * DIM + d;
    #pragma unroll 4
    for (int r = 0; r < 128; r++) s += q[base + r * NHEAD * DIM];
    pqg[(h * NQ + qb) * DIM + d] = s;
}

__global__ void pk_pool_kernel(const float* __restrict__ k) {
    int kb = blockIdx.x, h = blockIdx.y, d = threadIdx.x;
    float s = 0.f;
    int base = ((kb * 64) * NHEAD + h) * DIM + d;
    #pragma unroll 4
    for (int r = 0; r < 64; r++) s += k[base + r * NHEAD * DIM];
    pkg[(h * NK + kb) * DIM + d] = s;
}

__global__ void meank_kernel() {
    int h = blockIdx.x, d = threadIdx.x;
    float s = 0.f;
    #pragma unroll 4
    for (int kb = 0; kb < NK; kb++) s += pkg[(h * NK + kb) * DIM + d];
    mkg[h * DIM + d] = s * (1.f / (float)L_SEQ);
}

// ---------------- routing scores + top-32 selection -------------------------
__global__ void score_topk_kernel() {
    __shared__ float pqsh[DIM];
    __shared__ float mksh[DIM];
    __shared__ float pks[NK * 129];
    __shared__ float scores[NK];
    int qb = blockIdx.x, h = blockIdx.y, tid = threadIdx.x;
    pqsh[tid] = pqg[(h * NQ + qb) * DIM + tid];
    mksh[tid] = mkg[h * DIM + tid];
    for (int i = 0; i < 64; i++) {
        int idx = tid + i * 128;
        int kb = idx >> 7, d = idx & 127;
        pks[kb * 129 + d] = pkg[(h * NK + kb) * DIM + d];
    }
    __syncthreads();
    if (tid < NK) {
        float sc = 0.f;
        #pragma unroll 4
        for (int d = 0; d < DIM; d++)
            sc += pqsh[d] * (pks[tid * 129 + d] * (1.f / 64.f) - mksh[d]);
        scores[tid] = sc;
    }
    __syncthreads();
    if (tid == 0) {
        unsigned long long used = 0ull;
        for (int i = 0; i < TOPK; i++) {
            float best = -INFINITY; int bidx = 0;
            for (int kb = 0; kb < NK; kb++) {
                if ((used >> kb) & 1ull) continue;
                if (scores[kb] > best) { best = scores[kb]; bidx = kb; }
            }
            used |= 1ull << bidx;
            lutg[(h * NQ + qb) * TOPK + i] = bidx;
        }
    }
}

// ---------------- kv = fk^T v per head (+ ksum) -----------------------------
__global__ void kv_kernel(const float* __restrict__ v) {
    extern __shared__ float sm[];
    float* fksh = sm;            // 64x128
    float* vsh  = sm + 8192;     // 64x128
    int tid = threadIdx.x, h = blockIdx.y;
    int l0 = blockIdx.x * 64;
    const float4* fk4 = (const float4*)fkg;
    const float4* v4  = (const float4*)v;
    #pragma unroll
    for (int i = 0; i < 8; i++) {
        int idx = tid + i * 256;
        int row = idx >> 5, d4 = idx & 31;
        int g = (l0 + row) * (NHEAD * DIM / 4) + h * 32 + d4;
        ((float4*)fksh)[row * 32 + d4] = fk4[g];
        ((float4*)vsh)[row * 32 + d4]  = v4[g];
    }
    __syncthreads();
    int d = tid >> 1, eh4 = (tid & 1) * 16;
    float4 acc[16];
    #pragma unroll
    for (int i = 0; i < 16; i++) acc[i] = make_float4(0.f, 0.f, 0.f, 0.f);
    float ks = 0.f;
    for (int r = 0; r < 64; r++) {
        float a = fksh[r * DIM + d];
        if ((tid & 1) == 0) ks += a;
        #pragma unroll
        for (int i = 0; i < 16; i++) {
            float4 vv = ((float4*)vsh)[r * 32 + eh4 + i];
            acc[i].x += a * vv.x; acc[i].y += a * vv.y;
            acc[i].z += a * vv.z; acc[i].w += a * vv.w;
        }
    }
    float* kvp = kvg + h * DIM * DIM + d * DIM + (tid & 1) * 64;
    #pragma unroll
    for (int i = 0; i < 16; i++) {
        atomicAdd(&kvp[i * 4 + 0], acc[i].x);
        atomicAdd(&kvp[i * 4 + 1], acc[i].y);
        atomicAdd(&kvp[i * 4 + 2], acc[i].z);
        atomicAdd(&kvp[i * 4 + 3], acc[i].w);
    }
    if ((tid & 1) == 0) atomicAdd(&ksumg[h * DIM + d], ks);
}

// ---------------- M = kv @ W^T per head ------------------------------------
__global__ void m_kernel(const float* __restrict__ w) {
    extern __shared__ float sm[];
    float* kvsh = sm;               // 128 x 129
    float* wts  = sm + 128 * 129;   // transposed W
    int tid = threadIdx.x, h = blockIdx.x;
    for (int i = 0; i < 64; i++) {
        int idx = tid + i * 256;
        int d = idx >> 7, dp = idx & 127;
        kvsh[d * 129 + dp] = kvg[h * DIM * DIM + idx];
        int dpp = idx & 127;
        wts[dpp * 132 + (idx >> 7)] = w[idx];
    }
    __syncthreads();
    int d = tid >> 1, eh4 = (tid & 1) * 16;
    float4 acc[16];
    #pragma unroll
    for (int i = 0; i < 16; i++) acc[i] = make_float4(0.f, 0.f, 0.f, 0.f);
    for (int dp = 0; dp < DIM; dp++) {
        float a = kvsh[d * 129 + dp];
        #pragma unroll
        for (int i = 0; i < 16; i++) {
            float4 wv = ((float4*)(wts + dp * 132))[eh4 + i];
            acc[i].x += a * wv.x; acc[i].y += a * wv.y;
            acc[i].z += a * wv.z; acc[i].w += a * wv.w;
        }
    }
    float4* mp = (float4*)(Mg + h * DIM * DIM + d * DIM + (tid & 1) * 64);
    #pragma unroll
    for (int i = 0; i < 16; i++) mp[i] = acc[i];
}

// ---------------- linear-attn output (writes d_out) -------------------------
__global__ void lin_out_kernel(const float* __restrict__ b,
                               float* __restrict__ out) {
    __shared__ float fqsh[16 * DIM];
    __shared__ float sden[16];
    int tid = threadIdx.x, h = blockIdx.y;
    int l0 = blockIdx.x * 16;
    float ks = ksumg[h * DIM + tid];
    if (tid < 16) sden[tid] = 0.f;
    #pragma unroll
    for (int r = 0; r < 16; r++)
        fqsh[r * DIM + tid] = fqg[((l0 + r) * NHEAD + h) * DIM + tid];
    __syncthreads();
    int lane = tid & 31;
    #pragma unroll
    for (int r = 0; r < 16; r++) {
        float val = fqsh[r * DIM + tid] * ks;
        #pragma unroll
        for (int o = 16; o; o >>= 1) val += __shfl_xor_sync(0xffffffffu, val, o);
        if (lane == 0) atomicAdd(&sden[r], val);
    }
    __syncthreads();
    float accs[16];
    #pragma unroll
    for (int r = 0; r < 16; r++) accs[r] = 0.f;
    const float* Mp = Mg + h * DIM * DIM + tid;
    #pragma unroll 4
    for (int d = 0; d < DIM; d++) {
        float m = Mp[d * DIM];
        #pragma unroll
        for (int r = 0; r < 16; r++) accs[r] += fqsh[r * DIM + d] * m;
    }
    float be = b[tid];
    #pragma unroll
    for (int r = 0; r < 16; r++) {
        float inv = 1.f / (1e-5f + sden[r]);
        out[((l0 + r) * NHEAD + h) * DIM + tid] = accs[r] * inv + be;
    }
}

// ---------------- block-sparse attention v3 (tensor cores) ------------------
// grid (NQ, NHEAD), block 256 (8 warps x 16 query rows).
// K in smem as tf32, row stride 132 words (conflict-free B frags).
// V in smem as half2 pairs [d][kp], row stride 36 words (conflict-free).
// QK: m16n8k8 tf32; softmax in fragments; PV: m16n8k16 f16.
#define KS_STRIDE 132
#define VS_STRIDE 36
#define KBUF (64 * KS_STRIDE)     // 8448 u32
#define VBUF (128 * VS_STRIDE)    // 4608 u32
#define VS_BASE (2 * KBUF)        // u32 offset of V buffers

__global__ void __launch_bounds__(256, 1)
sparse_attn_kernel(const float* __restrict__ q,
                   float* __restrict__ out) {
    extern __shared__ u32 sm32[];
    const int tid = threadIdx.x;
    const int lane = tid & 31, wq = tid >> 5;
    const int qb = blockIdx.x, h = blockIdx.y;
    const int l0 = qb * 128;
    const float scale = 0.08838834764831845f;   // 1/sqrt(128)
    const int* lrow = lutg + (h * NQ + qb) * TOPK;
    const int g = lane >> 2, cq = lane & 3;

    unsigned smem_b = (unsigned)__cvta_generic_to_shared(sm32);

    // ---- issue tile 0 loads ----
    {
        int kb = lrow[0];
        u32 kbase = (u32)(h * NK + kb) * 64 * DIM;
        u32 vbase = (u32)(h * NK + kb) * DIM * 32;
        #pragma unroll
        for (int i = 0; i < 8; i++) {
            int idx = tid + i * 256;
            int row = idx >> 5, c4 = idx & 31;
            CP_ASYNC16(smem_b + (row * KS_STRIDE + c4 * 4) * 4,
                       (const void*)(ktg + kbase + row * DIM + c4 * 4));
        }
        #pragma unroll
        for (int i = 0; i < 4; i++) {
            int idx = tid + i * 256;
            int n = idx >> 3, c = idx & 7;
            CP_ASYNC16(smem_b + (VS_BASE + n * VS_STRIDE + c * 4) * 4,
                       (const void*)(vtg + vbase + n * 32 + c * 4));
        }
        CP_COMMIT();
    }

    // ---- load Q fragments (tf32, scaled) -----
    u32 qA[16][4];
    {
        int r_lo = l0 + wq * 16 + g;
        const float* q0 = q + (r_lo * NHEAD + h) * DIM;
        const float* q1 = q + ((r_lo + 8) * NHEAD + h) * DIM;
        #pragma unroll
        for (int s = 0; s < 16; s++) {
            qA[s][0] = f2tf32(q0[cq + 8 * s] * scale);
            qA[s][1] = f2tf32(q1[cq + 8 * s] * scale);
            qA[s][2] = f2tf32(q0[cq + 4 + 8 * s] * scale);
            qA[s][3] = f2tf32(q1[cq + 4 + 8 * s] * scale);
        }
    }

    float oc[16][4];
    #pragma unroll
    for (int i = 0; i < 16; i++) { oc[i][0] = oc[i][1] = oc[i][2] = oc[i][3] = 0.f; }
    float m_lo = -INFINITY, m_hi = -INFINITY, l_lo = 0.f, l_hi = 0.f;

    for (int t = 0; t < TOPK; t++) {
        const u32* Kc = sm32 + (t & 1) * KBUF;
        const u32* Vc = sm32 + VS_BASE + (t & 1) * VBUF;

        __syncthreads();                        // prev compute done, buffers free
        if (t + 1 < TOPK) {
            int kb = lrow[t + 1];
            int bb = (t + 1) & 1;
            u32 kbase = (u32)(h * NK + kb) * 64 * DIM;
            u32 vbase = (u32)(h * NK + kb) * DIM * 32;
            #pragma unroll
            for (int i = 0; i < 8; i++) {
                int idx = tid + i * 256;
                int row = idx >> 5, c4 = idx & 31;
                CP_ASYNC16(smem_b + (bb * KBUF + row * KS_STRIDE + c4 * 4) * 4,
                           (const void*)(ktg + kbase + row * DIM + c4 * 4));
            }
            #pragma unroll
            for (int i = 0; i < 4; i++) {
                int idx = tid + i * 256;
                int n = idx >> 3, c = idx & 7;
                CP_ASYNC16(smem_b + (VS_BASE + bb * VBUF + n * VS_STRIDE + c * 4) * 4,
                           (const void*)(vtg + vbase + n * 32 + c * 4));
            }
            CP_COMMIT();
            asm volatile("cp.async.wait_group 1;");
        } else {
            asm volatile("cp.async.wait_group 0;");
        }
        __syncthreads();                        // tile t visible

        // ---- S = Q K^T  (8 n-tiles of 8 keys, 16 k-steps) ----
        float sc[8][4];
        #pragma unroll
        for (int j = 0; j < 8; j++) { sc[j][0] = sc[j][1] = sc[j][2] = sc[j][3] = 0.f; }
        #pragma unroll
        for (int j = 0; j < 8; j++) {
            const u32* kcol = Kc + (g + 8 * j) * KS_STRIDE + cq;
            #pragma unroll
            for (int s = 0; s < 16; s++) {
                u32 b0 = kcol[8 * s];
                u32 b1 = kcol[8 * s + 4];
                mma_tf32(sc[j], qA[s], b0, b1);
            }
        }

        // ---- online softmax on fragments ----
        float mx_lo = -INFINITY, mx_hi = -INFINITY;
        #pragma unroll
        for (int j = 0; j < 8; j++) {
            mx_lo = fmaxf(mx_lo, fmaxf(sc[j][0], sc[j][1]));
            mx_hi = fmaxf(mx_hi, fmaxf(sc[j][2], sc[j][3]));
        }
        mx_lo = fmaxf(mx_lo, __shfl_xor_sync(0xffffffffu, mx_lo, 1));
        mx_lo = fmaxf(mx_lo, __shfl_xor_sync(0xffffffffu, mx_lo, 2));
        mx_hi = fmaxf(mx_hi, __shfl_xor_sync(0xffffffffu, mx_hi, 1));
        mx_hi = fmaxf(mx_hi, __shfl_xor_sync(0xffffffffu, mx_hi, 2));
        float mn_lo = fmaxf(m_lo, mx_lo), mn_hi = fmaxf(m_hi, mx_hi);
        float corr_lo = __expf(m_lo - mn_lo), corr_hi = __expf(m_hi - mn_hi);
        float ps_lo = 0.f, ps_hi = 0.f;
        #pragma unroll
        for (int j = 0; j < 8; j++) {
            sc[j][0] = __expf(sc[j][0] - mn_lo);
            sc[j][1] = __expf(sc[j][1] - mn_lo);
            sc[j][2] = __expf(sc[j][2] - mn_hi);
            sc[j][3] = __expf(sc[j][3] - mn_hi);
            ps_lo += sc[j][0] + sc[j][1];
            ps_hi += sc[j][2] + sc[j][3];
        }
        ps_lo += __shfl_xor_sync(0xffffffffu, ps_lo, 1);
        ps_lo += __shfl_xor_sync(0xffffffffu, ps_lo, 2);
        ps_hi += __shfl_xor_sync(0xffffffffu, ps_hi, 1);
        ps_hi += __shfl_xor_sync(0xffffffffu, ps_hi, 2);
        l_lo = l_lo * corr_lo + ps_lo;
        l_hi = l_hi * corr_hi + ps_hi;
        m_lo = mn_lo; m_hi = mn_hi;
        #pragma unroll
        for (int i = 0; i < 16; i++) {
            oc[i][0] *= corr_lo; oc[i][1] *= corr_lo;
            oc[i][2] *= corr_hi; oc[i][3] *= corr_hi;
        }

        // ---- O += P V  (fp16 A from S fragments, 4 k-steps, 16 n-tiles) ----
        #pragma unroll
        for (int T = 0; T < 4; T++) {
            u32 pa[4];
            pa[0] = pack_half2(sc[2 * T][0], sc[2 * T][1]);
            pa[1] = pack_half2(sc[2 * T][2], sc[2 * T][3]);
            pa[2] = pack_half2(sc[2 * T + 1][0], sc[2 * T + 1][1]);
            pa[3] = pack_half2(sc[2 * T + 1][2], sc[2 * T + 1][3]);
            const u32* vcol = Vc + g * VS_STRIDE + 8 * T + cq;
            #pragma unroll
            for (int nt = 0; nt < 16; nt++) {
                u32 b0 = vcol[nt * 8 * VS_STRIDE];
                u32 b1 = vcol[nt * 8 * VS_STRIDE + 4];
                mma_f16(oc[nt], pa, b0, b1);
            }
        }
    }

    // ---- epilogue: add into out ----
    float inv_lo = 1.f / l_lo, inv_hi = 1.f / l_hi;
    int r_lo = l0 + wq * 16 + g;
    #pragma unroll
    for (int nt = 0; nt < 16; nt++) {
        int col = 8 * nt + 2 * cq;
        float2* p0 = (float2*)&out[(r_lo * NHEAD + h) * DIM + col];
        float2 c0 = *p0;
        c0.x += oc[nt][0] * inv_lo; c0.y += oc[nt][1] * inv_lo;
        *p0 = c0;
        float2* p1 = (float2*)&out[((r_lo + 8) * NHEAD + h) * DIM + col];
        float2 c1 = *p1;
        c1.x += oc[nt][2] * inv_hi; c1.y += oc[nt][3] * inv_hi;
        *p1 = c1;
    }
}

// ---------------- launch -----------------------------------------------------
extern "C" void kernel_launch(void* const* d_in, const int* in_sizes, int n_in,
                              void* d_out, int out_size) {
    const float* q = (const float*)d_in[0];
    const float* k = (const float*)d_in[1];
    const float* v = (const float*)d_in[2];
    const float* w = (const float*)d_in[3];
    const float* b = (const float*)d_in[4];
    float* out = (float*)d_out;

    const int sparse_smem = (2 * KBUF + 2 * VBUF) * 4;   // 104448 bytes

    cudaFuncSetAttribute(kv_kernel, cudaFuncAttributeMaxDynamicSharedMemorySize, 65536);
    cudaFuncSetAttribute(m_kernel, cudaFuncAttributeMaxDynamicSharedMemorySize, 133632);
    cudaFuncSetAttribute(sparse_attn_kernel, cudaFuncAttributeMaxDynamicSharedMemorySize, sparse_smem);

    zero_kernel<<<64, 256>>>();
    prep_kv_kernel<<<dim3(NK, NHEAD), 256>>>(k, v);
    row_softmax_kernel<<<dim3(L_SEQ, NHEAD), 64>>>(q, k);
    pq_pool_kernel<<<dim3(NQ, NHEAD), 128>>>(q);
    pk_pool_kernel<<<dim3(NK, NHEAD), 128>>>(k);
    meank_kernel<<<NHEAD, 128>>>();
    score_topk_kernel<<<dim3(NQ, NHEAD), 128>>>();
    kv_kernel<<<dim3(64, NHEAD), 256, 65536>>>(v);
    m_kernel<<<NHEAD, 256, 133632>>>(w);
    lin_out_kernel<<<dim3(L_SEQ / 16, NHEAD), 128>>>(b, out);
    sparse_attn_kernel<<<dim3(NQ, NHEAD), 256, sparse_smem>>>(q, out);
}